// round 2
// baseline (speedup 1.0000x reference)
#include <cuda_runtime.h>
#include <math.h>

#define TT 1500
#define BB 16
#define DD 512
#define HH 1024
#define KEEPF 0.8f
#define EPSF 1e-5f
#define NTOT (TT*BB*HH)
#define GRID_SCAN 128
#define CPB 8            // output columns per CTA in the scan (128*8 = 1024)

// -------- scratch (device globals: no allocation allowed) --------
__device__ float g_wh[NTOT];            // BN(x@Wh^T) for current layer
__device__ float g_wz[NTOT];            // BN(x@Wz^T) for current layer
__device__ float g_h0[NTOT];            // layer-0 hidden sequence output
__device__ int   g_ctr[2*(TT+8)];       // per-step arrival counters, per layer

// =================================================================
// init: zero barrier counters; write x_len tail of the output
// =================================================================
__global__ void init_kernel(const int* __restrict__ x_len,
                            float* __restrict__ out, int out_size)
{
    int i = blockIdx.x * blockDim.x + threadIdx.x;
    if (i < 2*(TT+8)) g_ctr[i] = 0;
    if (out_size >= NTOT + BB && i < BB) out[NTOT + i] = (float)x_len[i];
}

// =================================================================
// fused GEMM + eval BatchNorm:
//   C[m][n] = bn( sum_k A[m][k] * W[n][k] )
// A: [M, K] row-major (M = T*B, divisible by 64), W: [1024, K], C: [M, 1024]
// tile: BM=64, BN=128, BK=8; 256 threads; 4x8 per-thread microtile
// =================================================================
__global__ void __launch_bounds__(256) gemm_bn_kernel(
    const float* __restrict__ A, const float* __restrict__ W,
    float* __restrict__ C,
    const float* __restrict__ gam, const float* __restrict__ bet,
    const float* __restrict__ mu,  const float* __restrict__ var,
    int K)
{
    __shared__ float As[8][68];    // [k][m], padded: conflict-free STS/LDS
    __shared__ float Bs[8][132];   // [k][n], padded

    int tid = threadIdx.x;
    int m0 = blockIdx.y * 64;
    int n0 = blockIdx.x * 128;

    int arow = tid >> 2;           // 0..63
    int acol = (tid & 3) * 2;      // 0,2,4,6
    int brow = tid >> 1;           // 0..127
    int bcol = (tid & 1) * 4;      // 0,4

    const float* Ap = A + (size_t)(m0 + arow) * K + acol;
    const float* Wp = W + (size_t)(n0 + brow) * K + bcol;

    float2 ar = *(const float2*)Ap;
    float4 br = *(const float4*)Wp;

    float acc[4][8];
    #pragma unroll
    for (int i = 0; i < 4; i++)
        #pragma unroll
        for (int j = 0; j < 8; j++) acc[i][j] = 0.f;

    int tx = tid & 15, ty = tid >> 4;
    int am = ty * 4, bn = tx * 8;
    int nk = K >> 3;

    for (int kt = 0; kt < nk; kt++) {
        As[acol  ][arow] = ar.x;
        As[acol+1][arow] = ar.y;
        Bs[bcol  ][brow] = br.x;
        Bs[bcol+1][brow] = br.y;
        Bs[bcol+2][brow] = br.z;
        Bs[bcol+3][brow] = br.w;
        __syncthreads();
        if (kt + 1 < nk) {
            ar = *(const float2*)(Ap + (size_t)(kt+1)*8);
            br = *(const float4*)(Wp + (size_t)(kt+1)*8);
        }
        #pragma unroll
        for (int kk = 0; kk < 8; kk++) {
            float4 a4 = *(const float4*)&As[kk][am];
            float4 b4 = *(const float4*)&Bs[kk][bn];
            float4 b5 = *(const float4*)&Bs[kk][bn+4];
            float av[4] = {a4.x, a4.y, a4.z, a4.w};
            float bv[8] = {b4.x, b4.y, b4.z, b4.w, b5.x, b5.y, b5.z, b5.w};
            #pragma unroll
            for (int i = 0; i < 4; i++)
                #pragma unroll
                for (int j = 0; j < 8; j++)
                    acc[i][j] = fmaf(av[i], bv[j], acc[i][j]);
        }
        __syncthreads();
    }

    // fused BN epilogue: y = g*(x-m)*rsqrt(v+eps)+b  ==  x*sc + sh
    float sc[8], sh[8];
    #pragma unroll
    for (int j = 0; j < 8; j++) {
        int n = n0 + bn + j;
        float inv = rsqrtf(var[n] + EPSF);
        sc[j] = gam[n] * inv;
        sh[j] = bet[n] - mu[n] * sc[j];
    }
    #pragma unroll
    for (int i = 0; i < 4; i++) {
        size_t row = (size_t)(m0 + am + i) * HH + n0 + bn;
        float4 o0, o1;
        o0.x = fmaf(acc[i][0], sc[0], sh[0]);
        o0.y = fmaf(acc[i][1], sc[1], sh[1]);
        o0.z = fmaf(acc[i][2], sc[2], sh[2]);
        o0.w = fmaf(acc[i][3], sc[3], sh[3]);
        o1.x = fmaf(acc[i][4], sc[4], sh[4]);
        o1.y = fmaf(acc[i][5], sc[5], sh[5]);
        o1.z = fmaf(acc[i][6], sc[6], sh[6]);
        o1.w = fmaf(acc[i][7], sc[7], sh[7]);
        *(float4*)(C + row)     = o0;
        *(float4*)(C + row + 4) = o1;
    }
}

// =================================================================
// persistent liGRU scan (one layer).
//   for t: z = sigmoid(WZ[t] + h @ Uz^T); a = WH[t] + h @ Uh^T;
//          h = z*h + (1-z)*relu(a)*KEEP;  Hout[t] = h
// 128 co-resident CTAs; CTA owns 8 columns, U-slices live in SMEM
// for all 1500 steps; full h staged into SMEM each step after a
// software grid barrier (per-step monotone counter).
// =================================================================
__global__ void __launch_bounds__(256, 1) scan_kernel(
    const float* __restrict__ WH, const float* __restrict__ WZ,
    const float* __restrict__ Uh, const float* __restrict__ Uz,
    float* __restrict__ Hout, int* __restrict__ ctr)
{
    extern __shared__ float smem[];
    float* Uzs = smem;               // [CPB][HH]
    float* Uhs = smem + CPB*HH;      // [CPB][HH]
    float* hs  = smem + 2*CPB*HH;    // [BB][HH]   (h_{t-1})

    int tid  = threadIdx.x;
    int w    = tid >> 5;
    int lane = tid & 31;
    int j0   = blockIdx.x * CPB;
    int nb   = gridDim.x;

    // load this CTA's U rows once (stationary for all steps)
    for (int idx = tid; idx < CPB*HH; idx += 256) {
        int r = idx >> 10, c = idx & (HH-1);
        Uzs[idx] = Uz[(size_t)(j0 + r)*HH + c];
        Uhs[idx] = Uh[(size_t)(j0 + r)*HH + c];
    }
    for (int idx = tid; idx < BB*HH; idx += 256) hs[idx] = 0.f;   // h0 = 0
    __syncthreads();

    int j = j0 + w;                      // this warp's output column
    const float* uzp = Uzs + w*HH;
    const float* uhp = Uhs + w*HH;

    for (int t = 0; t < TT; t++) {
        // prefetch this step's pre-projections early (overlaps with FMAs)
        float wzv = 0.f, whv = 0.f;
        int base = (t*BB + lane)*HH + j;
        if (lane < BB) { wzv = WZ[base]; whv = WH[base]; }

        float az[BB], ah[BB];
        #pragma unroll
        for (int b = 0; b < BB; b++) { az[b] = 0.f; ah[b] = 0.f; }

        // each lane covers k = i*64 + lane*2 (+1), 16 iterations
        #pragma unroll 2
        for (int i = 0; i < HH/64; i++) {
            int k = i*64 + lane*2;
            float2 uz2 = *(const float2*)(uzp + k);
            float2 uh2 = *(const float2*)(uhp + k);
            float2 hv[BB];
            #pragma unroll
            for (int b = 0; b < BB; b++)
                hv[b] = *(const float2*)(hs + b*HH + k);
            #pragma unroll
            for (int b = 0; b < BB; b++) {
                az[b] = fmaf(hv[b].x, uz2.x, az[b]);
                az[b] = fmaf(hv[b].y, uz2.y, az[b]);
                ah[b] = fmaf(hv[b].x, uh2.x, ah[b]);
                ah[b] = fmaf(hv[b].y, uh2.y, ah[b]);
            }
        }

        // warp butterfly reduce all 32 partial sums
        #pragma unroll
        for (int off = 16; off > 0; off >>= 1) {
            #pragma unroll
            for (int b = 0; b < BB; b++) {
                az[b] += __shfl_xor_sync(0xffffffffu, az[b], off);
                ah[b] += __shfl_xor_sync(0xffffffffu, ah[b], off);
            }
        }
        // lane b takes accumulator b (static-index select chain: no LMEM)
        float zsum = az[0], hsum = ah[0];
        #pragma unroll
        for (int b = 1; b < BB; b++)
            if (lane == b) { zsum = az[b]; hsum = ah[b]; }

        if (lane < BB) {
            float zt  = 1.f / (1.f + __expf(-(wzv + zsum)));
            float at  = whv + hsum;
            float hc  = fmaxf(at, 0.f) * KEEPF;
            float hold = hs[lane*HH + j];
            Hout[base] = zt*hold + (1.f - zt)*hc;
        }

        // grid barrier: release writes, arrive, spin on per-step counter
        __threadfence();
        __syncthreads();
        if (tid == 0) {
            atomicAdd(ctr + t, 1);
            while (*(volatile int*)(ctr + t) < nb) { }
        }
        __syncthreads();

        // stage h_t (written by all CTAs) into SMEM, L1-bypass loads
        const float4* src = (const float4*)(Hout + (size_t)t*BB*HH);
        float4* dst = (float4*)hs;
        for (int idx = tid; idx < BB*HH/4; idx += 256)
            dst[idx] = __ldcg(src + idx);
        __syncthreads();
    }
}

// =================================================================
extern "C" void kernel_launch(void* const* d_in, const int* in_sizes, int n_in,
                              void* d_out, int out_size)
{
    const float* x     = (const float*)d_in[0];
    const int*   x_len = (const int*)  d_in[1];
    const float* whW0  = (const float*)d_in[2];
    const float* wzW0  = (const float*)d_in[3];
    const float* uhW0  = (const float*)d_in[4];
    const float* uzW0  = (const float*)d_in[5];
    const float* bnh_g0 = (const float*)d_in[6];
    const float* bnh_b0 = (const float*)d_in[7];
    const float* bnh_m0 = (const float*)d_in[8];
    const float* bnh_v0 = (const float*)d_in[9];
    const float* bnz_g0 = (const float*)d_in[10];
    const float* bnz_b0 = (const float*)d_in[11];
    const float* bnz_m0 = (const float*)d_in[12];
    const float* bnz_v0 = (const float*)d_in[13];
    const float* whW1  = (const float*)d_in[14];
    const float* wzW1  = (const float*)d_in[15];
    const float* uhW1  = (const float*)d_in[16];
    const float* uzW1  = (const float*)d_in[17];
    const float* bnh_g1 = (const float*)d_in[18];
    const float* bnh_b1 = (const float*)d_in[19];
    const float* bnh_m1 = (const float*)d_in[20];
    const float* bnh_v1 = (const float*)d_in[21];
    const float* bnz_g1 = (const float*)d_in[22];
    const float* bnz_b1 = (const float*)d_in[23];
    const float* bnz_m1 = (const float*)d_in[24];
    const float* bnz_v1 = (const float*)d_in[25];

    float* out = (float*)d_out;

    float *p_wh, *p_wz, *p_h0; int* p_ctr;
    cudaGetSymbolAddress((void**)&p_wh, g_wh);
    cudaGetSymbolAddress((void**)&p_wz, g_wz);
    cudaGetSymbolAddress((void**)&p_h0, g_h0);
    cudaGetSymbolAddress((void**)&p_ctr, g_ctr);

    int smem_scan = (2*CPB*HH + BB*HH) * (int)sizeof(float);  // 128 KB
    cudaFuncSetAttribute(scan_kernel,
        cudaFuncAttributeMaxDynamicSharedMemorySize, smem_scan);

    init_kernel<<<16, 256>>>(x_len, out, out_size);

    dim3 gg(HH/128, (TT*BB)/64);   // (8, 375)

    // ---- layer 0 ----
    gemm_bn_kernel<<<gg, 256>>>(x, whW0, p_wh, bnh_g0, bnh_b0, bnh_m0, bnh_v0, DD);
    gemm_bn_kernel<<<gg, 256>>>(x, wzW0, p_wz, bnz_g0, bnz_b0, bnz_m0, bnz_v0, DD);
    scan_kernel<<<GRID_SCAN, 256, smem_scan>>>(p_wh, p_wz, uhW0, uzW0, p_h0, p_ctr);

    // ---- layer 1 (reads layer-0 hidden sequence) ----
    gemm_bn_kernel<<<gg, 256>>>(p_h0, whW1, p_wh, bnh_g1, bnh_b1, bnh_m1, bnh_v1, HH);
    gemm_bn_kernel<<<gg, 256>>>(p_h0, wzW1, p_wz, bnz_g1, bnz_b1, bnz_m1, bnz_v1, HH);
    scan_kernel<<<GRID_SCAN, 256, smem_scan>>>(p_wh, p_wz, uhW1, uzW1, out, p_ctr + (TT+8));
}

// round 3
// speedup vs baseline: 1.0057x; 1.0057x over previous
#include <cuda_runtime.h>
#include <math.h>

#define TT 1500
#define BB 16
#define DD 512
#define HH 1024
#define KEEPF 0.8f
#define EPSF 1e-5f
#define NTOT (TT*BB*HH)
#define GRID_SCAN 128
#define CPB 8
#define U_STRIDE 2052          // words per duplicated U row (2*1024 + 4 pad)

typedef unsigned long long u64;

// packed fp32x2 helpers (Blackwell FFMA2 path — only reachable via PTX)
#define FMA2(d,a,b,c) asm("fma.rn.f32x2 %0, %1, %2, %3;" : "=l"(d) : "l"(a), "l"(b), "l"(c))
#define PACK2(d,lo,hi) asm("mov.b64 %0, {%1, %2};" : "=l"(d) : "f"(lo), "f"(hi))

// -------- scratch (device globals: no allocation allowed) --------
__device__ float g_wh[NTOT];
__device__ float g_wz[NTOT];
__device__ float g_h0[NTOT];
__device__ float g_hT[HH*BB];         // transposed h_t broadcast buffer [k][b]
__device__ int   g_ctr[2*(TT+8)];

// =================================================================
__global__ void init_kernel(const int* __restrict__ x_len,
                            float* __restrict__ out, int out_size)
{
    int i = blockIdx.x * blockDim.x + threadIdx.x;
    if (i < 2*(TT+8)) g_ctr[i] = 0;
    if (out_size >= NTOT + BB && i < BB) out[NTOT + i] = (float)x_len[i];
}

// =================================================================
// fused GEMM + eval BatchNorm, fp32x2-packed accumulation.
// C[m][n] = bn( sum_k A[m][k]*W[n][k] ).  BM=64 BN=128 BK=8, 256 thr.
// A tile stored DUPLICATED along m (Asd[k][2m]=Asd[k][2m+1]=a) so the
// f32x2 broadcast operand comes straight out of an LDS.128.
// =================================================================
__global__ void __launch_bounds__(256) gemm_bn_kernel(
    const float* __restrict__ A, const float* __restrict__ W,
    float* __restrict__ C,
    const float* __restrict__ gam, const float* __restrict__ bet,
    const float* __restrict__ mu,  const float* __restrict__ var,
    int K)
{
    __shared__ float Asd[8][132];   // [k][2m] duplicated
    __shared__ float Bs[8][132];    // [k][n]

    int tid = threadIdx.x;
    int m0 = blockIdx.y * 64;
    int n0 = blockIdx.x * 128;

    int arow = tid >> 2;            // 0..63
    int acol = (tid & 3) * 2;       // 0,2,4,6
    int brow = tid >> 1;            // 0..127
    int bcol = (tid & 1) * 4;       // 0,4

    const float* Ap = A + (size_t)(m0 + arow) * K + acol;
    const float* Wp = W + (size_t)(n0 + brow) * K + bcol;

    float2 ar = *(const float2*)Ap;
    float4 br = *(const float4*)Wp;

    u64 acc[4][4];
    #pragma unroll
    for (int i = 0; i < 4; i++)
        #pragma unroll
        for (int j = 0; j < 4; j++) acc[i][j] = 0ull;

    int tx = tid & 15, ty = tid >> 4;
    int am2 = ty * 8;               // duplicated-m word offset (=2*(ty*4))
    int bn  = tx * 8;
    int nk = K >> 3;

    for (int kt = 0; kt < nk; kt++) {
        Asd[acol  ][2*arow] = ar.x;  Asd[acol  ][2*arow+1] = ar.x;
        Asd[acol+1][2*arow] = ar.y;  Asd[acol+1][2*arow+1] = ar.y;
        Bs[bcol  ][brow] = br.x;
        Bs[bcol+1][brow] = br.y;
        Bs[bcol+2][brow] = br.z;
        Bs[bcol+3][brow] = br.w;
        __syncthreads();
        if (kt + 1 < nk) {
            ar = *(const float2*)(Ap + (size_t)(kt+1)*8);
            br = *(const float4*)(Wp + (size_t)(kt+1)*8);
        }
        #pragma unroll
        for (int kk = 0; kk < 8; kk++) {
            ulonglong2 a01 = *(const ulonglong2*)&Asd[kk][am2];
            ulonglong2 a23 = *(const ulonglong2*)&Asd[kk][am2+4];
            ulonglong2 b01 = *(const ulonglong2*)&Bs[kk][bn];
            ulonglong2 b23 = *(const ulonglong2*)&Bs[kk][bn+4];
            u64 av[4] = {a01.x, a01.y, a23.x, a23.y};
            u64 bv[4] = {b01.x, b01.y, b23.x, b23.y};
            #pragma unroll
            for (int i = 0; i < 4; i++)
                #pragma unroll
                for (int j = 0; j < 4; j++)
                    FMA2(acc[i][j], av[i], bv[j], acc[i][j]);
        }
        __syncthreads();
    }

    // fused BN epilogue, packed
    float sc[8], sh[8];
    #pragma unroll
    for (int j = 0; j < 8; j++) {
        int n = n0 + bn + j;
        float inv = rsqrtf(var[n] + EPSF);
        sc[j] = gam[n] * inv;
        sh[j] = bet[n] - mu[n] * sc[j];
    }
    u64 sc2[4], sh2[4];
    #pragma unroll
    for (int j = 0; j < 4; j++) {
        PACK2(sc2[j], sc[2*j], sc[2*j+1]);
        PACK2(sh2[j], sh[2*j], sh[2*j+1]);
    }
    #pragma unroll
    for (int i = 0; i < 4; i++) {
        size_t row = (size_t)(m0 + ty*4 + i) * HH + n0 + bn;
        u64 o[4];
        #pragma unroll
        for (int j = 0; j < 4; j++) FMA2(o[j], acc[i][j], sc2[j], sh2[j]);
        ulonglong2 s0; s0.x = o[0]; s0.y = o[1];
        ulonglong2 s1; s1.x = o[2]; s1.y = o[3];
        *(ulonglong2*)(C + row)     = s0;
        *(ulonglong2*)(C + row + 4) = s1;
    }
}

// =================================================================
// persistent liGRU scan, split-K + fp32x2.
// 128 CTAs x 256 thr, 1 CTA/SM.  CTA owns 8 cols; U stored DUPLICATED
// in smem ([c][2k]); h_{t-1} staged k-major hs[k][b]; warp w covers
// k-slice [128w,128w+128) for all 8 cols x 16 b; smem reduction; grid
// barrier; h broadcast via transposed global scratch hT[k][b].
// =================================================================
__global__ void __launch_bounds__(256, 1) scan_kernel(
    const float* __restrict__ WH, const float* __restrict__ WZ,
    const float* __restrict__ Uh, const float* __restrict__ Uz,
    float* __restrict__ Hout, float* __restrict__ hT,
    int* __restrict__ ctr)
{
    extern __shared__ float smem[];
    float* Uzd = smem;                       // [8][U_STRIDE]
    float* Uhd = smem + 8*U_STRIDE;          // [8][U_STRIDE]
    float* hs  = smem + 16*U_STRIDE;         // [1024][16]
    float* red = hs + HH*BB;                 // [2048]

    int tid  = threadIdx.x;
    int w    = tid >> 5;
    int lane = tid & 31;
    int j0   = blockIdx.x * CPB;
    int nb   = gridDim.x;

    // stationary duplicated U load
    for (int idx = tid; idx < CPB*HH; idx += 256) {
        int r = idx >> 10, k = idx & (HH-1);
        float vz = Uz[(size_t)(j0 + r)*HH + k];
        float vh = Uh[(size_t)(j0 + r)*HH + k];
        *(float2*)(Uzd + r*U_STRIDE + 2*k) = make_float2(vz, vz);
        *(float2*)(Uhd + r*U_STRIDE + 2*k) = make_float2(vh, vh);
    }
    for (int idx = tid; idx < HH*BB; idx += 256) hs[idx] = 0.f;
    __syncthreads();

    int c = lane >> 2;                 // 0..7 local column
    int q = lane & 3;                  // 0..3 batch-quad
    const float* uzp = Uzd + c*U_STRIDE + (w << 8);   // 2*(w*128) words
    const float* uhp = Uhd + c*U_STRIDE + (w << 8);
    const float* hp  = hs + (w << 11) + (q << 2);     // row w*128, col 4q

    int bg = tid >> 3, cg = tid & 7;   // gating map for tid < 128
    int rb = (w << 8) + (c << 4) + (q << 2);

    for (int t = 0; t < TT; t++) {
        float wzv = 0.f, whv = 0.f;
        size_t obase = 0;
        if (tid < 128) {
            obase = ((size_t)t*BB + bg)*HH + (j0 + cg);
            wzv = WZ[obase]; whv = WH[obase];
        }

        u64 az0 = 0, az1 = 0, ah0 = 0, ah1 = 0;
        #pragma unroll 8
        for (int kk = 0; kk < 128; kk += 2) {
            ulonglong2 uz2 = *(const ulonglong2*)(uzp + 2*kk);
            ulonglong2 uh2 = *(const ulonglong2*)(uhp + 2*kk);
            ulonglong2 h0  = *(const ulonglong2*)(hp + (kk << 4));
            ulonglong2 h1  = *(const ulonglong2*)(hp + ((kk+1) << 4));
            FMA2(az0, h0.x, uz2.x, az0);  FMA2(az1, h0.y, uz2.x, az1);
            FMA2(ah0, h0.x, uh2.x, ah0);  FMA2(ah1, h0.y, uh2.x, ah1);
            FMA2(az0, h1.x, uz2.y, az0);  FMA2(az1, h1.y, uz2.y, az1);
            FMA2(ah0, h1.x, uh2.y, ah0);  FMA2(ah1, h1.y, uh2.y, ah1);
        }

        // per-warp partials -> smem:  red[w*256 + m*128 + c*16 + b]
        *(u64*)(red + rb)       = az0;
        *(u64*)(red + rb + 2)   = az1;
        *(u64*)(red + rb + 128) = ah0;
        *(u64*)(red + rb + 130) = ah1;
        __syncthreads();

        if (tid < 128) {
            float sz = 0.f, sa = 0.f;
            int o = cg*16 + bg;
            #pragma unroll
            for (int ww = 0; ww < 8; ww++) {
                sz += red[ww*256 + o];
                sa += red[ww*256 + 128 + o];
            }
            float zt = 1.f / (1.f + __expf(-(wzv + sz)));
            float at = whv + sa;
            float hc = fmaxf(at, 0.f) * KEEPF;
            float hold = hs[((j0 + cg) << 4) + bg];
            float hn = zt*hold + (1.f - zt)*hc;
            Hout[obase] = hn;
            hT[((j0 + cg) << 4) + bg] = hn;
        }

        __threadfence();
        __syncthreads();
        if (t == TT-1) break;

        if (tid == 0) {
            atomicAdd(ctr + t, 1);
            while (*((volatile int*)(ctr + t)) < nb) { }
        }
        __syncthreads();

        // coalesced reload of h_t into hs (k-major, linear copy)
        {
            const float4* src = (const float4*)hT;
            float4* dst = (float4*)hs;
            #pragma unroll
            for (int i = 0; i < 16; i++)
                dst[tid + (i << 8)] = __ldcg(src + tid + (i << 8));
        }
        __syncthreads();
    }
}

// =================================================================
extern "C" void kernel_launch(void* const* d_in, const int* in_sizes, int n_in,
                              void* d_out, int out_size)
{
    const float* x     = (const float*)d_in[0];
    const int*   x_len = (const int*)  d_in[1];
    const float* whW0  = (const float*)d_in[2];
    const float* wzW0  = (const float*)d_in[3];
    const float* uhW0  = (const float*)d_in[4];
    const float* uzW0  = (const float*)d_in[5];
    const float* bnh_g0 = (const float*)d_in[6];
    const float* bnh_b0 = (const float*)d_in[7];
    const float* bnh_m0 = (const float*)d_in[8];
    const float* bnh_v0 = (const float*)d_in[9];
    const float* bnz_g0 = (const float*)d_in[10];
    const float* bnz_b0 = (const float*)d_in[11];
    const float* bnz_m0 = (const float*)d_in[12];
    const float* bnz_v0 = (const float*)d_in[13];
    const float* whW1  = (const float*)d_in[14];
    const float* wzW1  = (const float*)d_in[15];
    const float* uhW1  = (const float*)d_in[16];
    const float* uzW1  = (const float*)d_in[17];
    const float* bnh_g1 = (const float*)d_in[18];
    const float* bnh_b1 = (const float*)d_in[19];
    const float* bnh_m1 = (const float*)d_in[20];
    const float* bnh_v1 = (const float*)d_in[21];
    const float* bnz_g1 = (const float*)d_in[22];
    const float* bnz_b1 = (const float*)d_in[23];
    const float* bnz_m1 = (const float*)d_in[24];
    const float* bnz_v1 = (const float*)d_in[25];

    float* out = (float*)d_out;

    float *p_wh, *p_wz, *p_h0, *p_hT; int* p_ctr;
    cudaGetSymbolAddress((void**)&p_wh, g_wh);
    cudaGetSymbolAddress((void**)&p_wz, g_wz);
    cudaGetSymbolAddress((void**)&p_h0, g_h0);
    cudaGetSymbolAddress((void**)&p_hT, g_hT);
    cudaGetSymbolAddress((void**)&p_ctr, g_ctr);

    int smem_scan = (16*U_STRIDE + HH*BB + 2048) * (int)sizeof(float);  // 205056 B
    cudaFuncSetAttribute(scan_kernel,
        cudaFuncAttributeMaxDynamicSharedMemorySize, smem_scan);

    init_kernel<<<16, 256>>>(x_len, out, out_size);

    dim3 gg(HH/128, (TT*BB)/64);   // (8, 375)

    // ---- layer 0 ----
    gemm_bn_kernel<<<gg, 256>>>(x, whW0, p_wh, bnh_g0, bnh_b0, bnh_m0, bnh_v0, DD);
    gemm_bn_kernel<<<gg, 256>>>(x, wzW0, p_wz, bnz_g0, bnz_b0, bnz_m0, bnz_v0, DD);
    scan_kernel<<<GRID_SCAN, 256, smem_scan>>>(p_wh, p_wz, uhW0, uzW0, p_h0, p_hT, p_ctr);

    // ---- layer 1 ----
    gemm_bn_kernel<<<gg, 256>>>(p_h0, whW1, p_wh, bnh_g1, bnh_b1, bnh_m1, bnh_v1, HH);
    gemm_bn_kernel<<<gg, 256>>>(p_h0, wzW1, p_wz, bnz_g1, bnz_b1, bnz_m1, bnz_v1, HH);
    scan_kernel<<<GRID_SCAN, 256, smem_scan>>>(p_wh, p_wz, uhW1, uzW1, out, p_hT, p_ctr + (TT+8));
}

// round 4
// speedup vs baseline: 1.1038x; 1.0976x over previous
#include <cuda_runtime.h>
#include <math.h>

#define TT 1500
#define BB 16
#define DD 512
#define HH 1024
#define KEEPF 0.8f
#define EPSF 1e-5f
#define NTOT (TT*BB*HH)
#define GRID_SCAN 128
#define HROW 17                     // padded hs row stride (floats)
#define REDS 65                     // padded red row stride (u64)
#define FPAD 32                     // ints per flag slot (128B)

typedef unsigned long long u64;

#define FMA2(d,a,b,c) asm("fma.rn.f32x2 %0, %1, %2, %3;" : "=l"(d) : "l"(a), "l"(b), "l"(c))
#define ADD2(d,a,b)   asm("add.rn.f32x2 %0, %1, %2;" : "=l"(d) : "l"(a), "l"(b))
#define PACK2(d,lo,hi) asm("mov.b64 %0, {%1, %2};" : "=l"(d) : "f"(lo), "f"(hi))
#define UNPACK2(lo,hi,in) asm("mov.b64 {%0, %1}, %2;" : "=f"(lo), "=f"(hi) : "l"(in))

// -------- scratch (device globals: no allocation allowed) --------
__device__ float g_wh[NTOT];
__device__ float g_wz[NTOT];
__device__ float g_h0[NTOT];
__device__ float g_hT[HH*BB];          // h_t broadcast buffer [k][b]
__device__ int   g_flags[2*GRID_SCAN*FPAD];

// =================================================================
__global__ void init_kernel(const int* __restrict__ x_len,
                            float* __restrict__ out, int out_size)
{
    int i = blockIdx.x * blockDim.x + threadIdx.x;
    if (i < 2*GRID_SCAN*FPAD) g_flags[i] = 0;
    if (out_size >= NTOT + BB && i < BB) out[NTOT + i] = (float)x_len[i];
}

// =================================================================
// fused GEMM + eval BatchNorm (unchanged from R3, fp32x2-packed)
// =================================================================
__global__ void __launch_bounds__(256) gemm_bn_kernel(
    const float* __restrict__ A, const float* __restrict__ W,
    float* __restrict__ C,
    const float* __restrict__ gam, const float* __restrict__ bet,
    const float* __restrict__ mu,  const float* __restrict__ var,
    int K)
{
    __shared__ float Asd[8][132];
    __shared__ float Bs[8][132];

    int tid = threadIdx.x;
    int m0 = blockIdx.y * 64;
    int n0 = blockIdx.x * 128;

    int arow = tid >> 2;
    int acol = (tid & 3) * 2;
    int brow = tid >> 1;
    int bcol = (tid & 1) * 4;

    const float* Ap = A + (size_t)(m0 + arow) * K + acol;
    const float* Wp = W + (size_t)(n0 + brow) * K + bcol;

    float2 ar = *(const float2*)Ap;
    float4 br = *(const float4*)Wp;

    u64 acc[4][4];
    #pragma unroll
    for (int i = 0; i < 4; i++)
        #pragma unroll
        for (int j = 0; j < 4; j++) acc[i][j] = 0ull;

    int tx = tid & 15, ty = tid >> 4;
    int am2 = ty * 8;
    int bn  = tx * 8;
    int nk = K >> 3;

    for (int kt = 0; kt < nk; kt++) {
        Asd[acol  ][2*arow] = ar.x;  Asd[acol  ][2*arow+1] = ar.x;
        Asd[acol+1][2*arow] = ar.y;  Asd[acol+1][2*arow+1] = ar.y;
        Bs[bcol  ][brow] = br.x;
        Bs[bcol+1][brow] = br.y;
        Bs[bcol+2][brow] = br.z;
        Bs[bcol+3][brow] = br.w;
        __syncthreads();
        if (kt + 1 < nk) {
            ar = *(const float2*)(Ap + (size_t)(kt+1)*8);
            br = *(const float4*)(Wp + (size_t)(kt+1)*8);
        }
        #pragma unroll
        for (int kk = 0; kk < 8; kk++) {
            ulonglong2 a01 = *(const ulonglong2*)&Asd[kk][am2];
            ulonglong2 a23 = *(const ulonglong2*)&Asd[kk][am2+4];
            ulonglong2 b01 = *(const ulonglong2*)&Bs[kk][bn];
            ulonglong2 b23 = *(const ulonglong2*)&Bs[kk][bn+4];
            u64 av[4] = {a01.x, a01.y, a23.x, a23.y};
            u64 bv[4] = {b01.x, b01.y, b23.x, b23.y};
            #pragma unroll
            for (int i = 0; i < 4; i++)
                #pragma unroll
                for (int j = 0; j < 4; j++)
                    FMA2(acc[i][j], av[i], bv[j], acc[i][j]);
        }
        __syncthreads();
    }

    float sc[8], sh[8];
    #pragma unroll
    for (int j = 0; j < 8; j++) {
        int n = n0 + bn + j;
        float inv = rsqrtf(var[n] + EPSF);
        sc[j] = gam[n] * inv;
        sh[j] = bet[n] - mu[n] * sc[j];
    }
    u64 sc2[4], sh2[4];
    #pragma unroll
    for (int j = 0; j < 4; j++) {
        PACK2(sc2[j], sc[2*j], sc[2*j+1]);
        PACK2(sh2[j], sh[2*j], sh[2*j+1]);
    }
    #pragma unroll
    for (int i = 0; i < 4; i++) {
        size_t row = (size_t)(m0 + ty*4 + i) * HH + n0 + bn;
        u64 o[4];
        #pragma unroll
        for (int j = 0; j < 4; j++) FMA2(o[j], acc[i][j], sc2[j], sh2[j]);
        ulonglong2 s0; s0.x = o[0]; s0.y = o[1];
        ulonglong2 s1; s1.x = o[2]; s1.y = o[3];
        *(ulonglong2*)(C + row)     = s0;
        *(ulonglong2*)(C + row + 4) = s1;
    }
}

// =================================================================
// persistent liGRU scan, register-stationary U.
// 128 CTAs x 256 thr, 1/SM. thread = (cg=tid>>6: col-pair, kg=tid&63:
// k-slice {kg + 64*kk}).  U held in 64 f32x2 registers for ALL steps.
// Per step: h read from smem (scalar LDS, padded rows, conflict-free),
// col-pair-packed FFMA2, k-partial reduction via smem, gate on 64 thr,
// release/acquire flag barrier, h broadcast reload via global hT.
// =================================================================
__global__ void __launch_bounds__(256, 1) scan_kernel(
    const float* __restrict__ WH, const float* __restrict__ WZ,
    const float* __restrict__ Uh, const float* __restrict__ Uz,
    float* __restrict__ Hout, float* __restrict__ hT,
    int* __restrict__ flags)
{
    extern __shared__ float smem[];
    float* hs  = smem;                        // [1024][HROW]
    u64*   red = (u64*)(smem + HH*HROW + 2);  // [128][REDS], 16B-aligned base

    int tid = threadIdx.x;
    int cg  = tid >> 6;            // 0..3  col-pair
    int kg  = tid & 63;            // 0..63 k-slice
    int j0  = blockIdx.x * 8;

    // ---- stationary U in registers: (U[c0][k], U[c1][k]) pairs ----
    u64 uz2[16], uh2[16];
    {
        const float* uzr0 = Uz + (size_t)(j0 + 2*cg)*HH;
        const float* uzr1 = uzr0 + HH;
        const float* uhr0 = Uh + (size_t)(j0 + 2*cg)*HH;
        const float* uhr1 = uhr0 + HH;
        #pragma unroll
        for (int kk = 0; kk < 16; kk++) {
            int k = kg + (kk << 6);
            PACK2(uz2[kk], uzr0[k], uzr1[k]);
            PACK2(uh2[kk], uhr0[k], uhr1[k]);
        }
    }
    for (int idx = tid; idx < HH*HROW; idx += 256) hs[idx] = 0.f;  // h0 = 0
    __syncthreads();

    // gating-thread constants (tid < 64): b = tid&15, cgo = tid>>4
    int b_o  = tid & 15;
    int cg_o = tid >> 4;
    int jg   = j0 + 2*cg_o;

    for (int t = 0; t < TT; t++) {
        // prefetch this step's pre-projections (DRAM latency hidden by FMAs)
        float wz0=0.f, wz1=0.f, wh0=0.f, wh1=0.f;
        size_t ob = 0;
        if (tid < 64) {
            ob = ((size_t)t*BB + b_o)*HH + jg;
            float2 z2 = *(const float2*)(WZ + ob);
            float2 h2 = *(const float2*)(WH + ob);
            wz0 = z2.x; wz1 = z2.y; wh0 = h2.x; wh1 = h2.y;
        }

        // ---- compute: az2[b] = (sum_k Uz[c0,k]h[k,b], sum Uz[c1,k]h[k,b]) ----
        u64 az2[16], ah2[16];
        #pragma unroll
        for (int b = 0; b < 16; b++) { az2[b] = 0ull; ah2[b] = 0ull; }

        const float* hbase = hs + kg * HROW;
        #pragma unroll
        for (int kk = 0; kk < 16; kk++) {
            const float* hr = hbase + (kk << 6) * HROW;
            #pragma unroll
            for (int b = 0; b < 16; b++) {
                float hv = hr[b];
                u64 hd; PACK2(hd, hv, hv);
                FMA2(az2[b], hd, uz2[kk], az2[b]);
                FMA2(ah2[b], hd, uh2[kk], ah2[b]);
            }
        }

        // ---- k-partial write: red[p][kg], p = (cg*16+b)*2 + m ----
        {
            u64* rp = red + (size_t)(cg*16)*2*REDS + kg;
            #pragma unroll
            for (int b = 0; b < 16; b++) {
                rp[(2*b  )*REDS] = az2[b];
                rp[(2*b+1)*REDS] = ah2[b];
            }
        }
        __syncthreads();

        // ---- reduce + gate on 64 threads ----
        if (tid < 64) {
            const u64* rz = red + (size_t)((cg_o*16 + b_o)*2)*REDS;
            const u64* ra = rz + REDS;
            u64 sz = 0ull, sa = 0ull;
            #pragma unroll
            for (int i = 0; i < 64; i++) {
                ADD2(sz, sz, rz[i]);
                ADD2(sa, sa, ra[i]);
            }
            float z0,z1,a0,a1;
            UNPACK2(z0, z1, sz);
            UNPACK2(a0, a1, sa);

            float zt0 = 1.f / (1.f + __expf(-(wz0 + z0)));
            float zt1 = 1.f / (1.f + __expf(-(wz1 + z1)));
            float hc0 = fmaxf(wh0 + a0, 0.f) * KEEPF;
            float hc1 = fmaxf(wh1 + a1, 0.f) * KEEPF;
            float ho0 = hs[jg*HROW + b_o];
            float ho1 = hs[(jg+1)*HROW + b_o];
            float hn0 = zt0*ho0 + (1.f - zt0)*hc0;
            float hn1 = zt1*ho1 + (1.f - zt1)*hc1;
            float2 o2; o2.x = hn0; o2.y = hn1;
            *(float2*)(Hout + ob) = o2;
            hT[jg*BB + b_o]     = hn0;
            hT[(jg+1)*BB + b_o] = hn1;
        }
        __syncthreads();
        if (t == TT-1) break;

        // ---- release/acquire distributed-flag grid barrier ----
        if (tid == 0) {
            asm volatile("st.release.gpu.global.s32 [%0], %1;"
                         :: "l"(flags + blockIdx.x*FPAD), "r"(t+1) : "memory");
        }
        if (tid < GRID_SCAN) {
            const int* fp = flags + tid*FPAD;
            int v;
            do {
                asm volatile("ld.acquire.gpu.global.s32 %0, [%1];"
                             : "=r"(v) : "l"(fp) : "memory");
            } while (v <= t);
        }
        __syncthreads();

        // ---- broadcast reload: hT [k][b] -> hs padded rows ----
        #pragma unroll
        for (int ii = 0; ii < 2; ii++) {
            float4 v[8];
            #pragma unroll
            for (int i = 0; i < 8; i++)
                v[i] = __ldcg((const float4*)hT + (tid + ((ii*8 + i) << 8)));
            #pragma unroll
            for (int i = 0; i < 8; i++) {
                int f = tid + ((ii*8 + i) << 8);
                float* d = hs + (f >> 2)*HROW + ((f & 3) << 2);
                d[0]=v[i].x; d[1]=v[i].y; d[2]=v[i].z; d[3]=v[i].w;
            }
        }
        __syncthreads();
    }
}

// =================================================================
extern "C" void kernel_launch(void* const* d_in, const int* in_sizes, int n_in,
                              void* d_out, int out_size)
{
    const float* x     = (const float*)d_in[0];
    const int*   x_len = (const int*)  d_in[1];
    const float* whW0  = (const float*)d_in[2];
    const float* wzW0  = (const float*)d_in[3];
    const float* uhW0  = (const float*)d_in[4];
    const float* uzW0  = (const float*)d_in[5];
    const float* bnh_g0 = (const float*)d_in[6];
    const float* bnh_b0 = (const float*)d_in[7];
    const float* bnh_m0 = (const float*)d_in[8];
    const float* bnh_v0 = (const float*)d_in[9];
    const float* bnz_g0 = (const float*)d_in[10];
    const float* bnz_b0 = (const float*)d_in[11];
    const float* bnz_m0 = (const float*)d_in[12];
    const float* bnz_v0 = (const float*)d_in[13];
    const float* whW1  = (const float*)d_in[14];
    const float* wzW1  = (const float*)d_in[15];
    const float* uhW1  = (const float*)d_in[16];
    const float* uzW1  = (const float*)d_in[17];
    const float* bnh_g1 = (const float*)d_in[18];
    const float* bnh_b1 = (const float*)d_in[19];
    const float* bnh_m1 = (const float*)d_in[20];
    const float* bnh_v1 = (const float*)d_in[21];
    const float* bnz_g1 = (const float*)d_in[22];
    const float* bnz_b1 = (const float*)d_in[23];
    const float* bnz_m1 = (const float*)d_in[24];
    const float* bnz_v1 = (const float*)d_in[25];

    float* out = (float*)d_out;

    float *p_wh, *p_wz, *p_h0, *p_hT; int* p_fl;
    cudaGetSymbolAddress((void**)&p_wh, g_wh);
    cudaGetSymbolAddress((void**)&p_wz, g_wz);
    cudaGetSymbolAddress((void**)&p_h0, g_h0);
    cudaGetSymbolAddress((void**)&p_hT, g_hT);
    cudaGetSymbolAddress((void**)&p_fl, g_flags);

    int smem_scan = (HH*HROW + 2) * (int)sizeof(float)
                  + 128*REDS * (int)sizeof(u64);      // ~136 KB
    cudaFuncSetAttribute(scan_kernel,
        cudaFuncAttributeMaxDynamicSharedMemorySize, smem_scan);

    init_kernel<<<32, 256>>>(x_len, out, out_size);

    dim3 gg(HH/128, (TT*BB)/64);   // (8, 375)

    // ---- layer 0 ----
    gemm_bn_kernel<<<gg, 256>>>(x, whW0, p_wh, bnh_g0, bnh_b0, bnh_m0, bnh_v0, DD);
    gemm_bn_kernel<<<gg, 256>>>(x, wzW0, p_wz, bnz_g0, bnz_b0, bnz_m0, bnz_v0, DD);
    scan_kernel<<<GRID_SCAN, 256, smem_scan>>>(p_wh, p_wz, uhW0, uzW0, p_h0, p_hT, p_fl);

    // ---- layer 1 ----
    gemm_bn_kernel<<<gg, 256>>>(p_h0, whW1, p_wh, bnh_g1, bnh_b1, bnh_m1, bnh_v1, HH);
    gemm_bn_kernel<<<gg, 256>>>(p_h0, wzW1, p_wz, bnz_g1, bnz_b1, bnz_m1, bnz_v1, HH);
    scan_kernel<<<GRID_SCAN, 256, smem_scan>>>(p_wh, p_wz, uhW1, uzW1, out, p_hT,
                                               p_fl + GRID_SCAN*FPAD);
}

// round 5
// speedup vs baseline: 1.1851x; 1.0737x over previous
#include <cuda_runtime.h>
#include <math.h>

#define TT 1500
#define BB 16
#define DD 512
#define HH 1024
#define KEEPF 0.8f
#define EPSF 1e-5f
#define NTOT (TT*BB*HH)
#define GRID_SCAN 128
#define REDS 65                     // padded red row stride (u64)
#define FPAD 32                     // ints per flag slot (128B)

typedef unsigned long long u64;

#define FMA2(d,a,b,c) asm("fma.rn.f32x2 %0, %1, %2, %3;" : "=l"(d) : "l"(a), "l"(b), "l"(c))
#define ADD2(d,a,b)   asm("add.rn.f32x2 %0, %1, %2;" : "=l"(d) : "l"(a), "l"(b))
#define PACK2(d,lo,hi) asm("mov.b64 %0, {%1, %2};" : "=l"(d) : "f"(lo), "f"(hi))
#define UNPACK2(lo,hi,in) asm("mov.b64 {%0, %1}, %2;" : "=f"(lo), "=f"(hi) : "l"(in))

// -------- scratch (device globals: no allocation allowed) --------
__device__ float g_wh[NTOT];
__device__ float g_wz[NTOT];
__device__ float g_h0[NTOT];
__device__ float g_hT[BB*HH];          // h_t broadcast buffer, [b][k]
__device__ int   g_flags[2*GRID_SCAN*FPAD];

// =================================================================
__global__ void init_kernel(const int* __restrict__ x_len,
                            float* __restrict__ out, int out_size)
{
    int i = blockIdx.x * blockDim.x + threadIdx.x;
    if (i < 2*GRID_SCAN*FPAD) g_flags[i] = 0;
    if (out_size >= NTOT + BB && i < BB) out[NTOT + i] = (float)x_len[i];
}

// =================================================================
// fused GEMM + eval BatchNorm (unchanged, fp32x2-packed)
// =================================================================
__global__ void __launch_bounds__(256) gemm_bn_kernel(
    const float* __restrict__ A, const float* __restrict__ W,
    float* __restrict__ C,
    const float* __restrict__ gam, const float* __restrict__ bet,
    const float* __restrict__ mu,  const float* __restrict__ var,
    int K)
{
    __shared__ float Asd[8][132];
    __shared__ float Bs[8][132];

    int tid = threadIdx.x;
    int m0 = blockIdx.y * 64;
    int n0 = blockIdx.x * 128;

    int arow = tid >> 2;
    int acol = (tid & 3) * 2;
    int brow = tid >> 1;
    int bcol = (tid & 1) * 4;

    const float* Ap = A + (size_t)(m0 + arow) * K + acol;
    const float* Wp = W + (size_t)(n0 + brow) * K + bcol;

    float2 ar = *(const float2*)Ap;
    float4 br = *(const float4*)Wp;

    u64 acc[4][4];
    #pragma unroll
    for (int i = 0; i < 4; i++)
        #pragma unroll
        for (int j = 0; j < 4; j++) acc[i][j] = 0ull;

    int tx = tid & 15, ty = tid >> 4;
    int am2 = ty * 8;
    int bn  = tx * 8;
    int nk = K >> 3;

    for (int kt = 0; kt < nk; kt++) {
        Asd[acol  ][2*arow] = ar.x;  Asd[acol  ][2*arow+1] = ar.x;
        Asd[acol+1][2*arow] = ar.y;  Asd[acol+1][2*arow+1] = ar.y;
        Bs[bcol  ][brow] = br.x;
        Bs[bcol+1][brow] = br.y;
        Bs[bcol+2][brow] = br.z;
        Bs[bcol+3][brow] = br.w;
        __syncthreads();
        if (kt + 1 < nk) {
            ar = *(const float2*)(Ap + (size_t)(kt+1)*8);
            br = *(const float4*)(Wp + (size_t)(kt+1)*8);
        }
        #pragma unroll
        for (int kk = 0; kk < 8; kk++) {
            ulonglong2 a01 = *(const ulonglong2*)&Asd[kk][am2];
            ulonglong2 a23 = *(const ulonglong2*)&Asd[kk][am2+4];
            ulonglong2 b01 = *(const ulonglong2*)&Bs[kk][bn];
            ulonglong2 b23 = *(const ulonglong2*)&Bs[kk][bn+4];
            u64 av[4] = {a01.x, a01.y, a23.x, a23.y};
            u64 bv[4] = {b01.x, b01.y, b23.x, b23.y};
            #pragma unroll
            for (int i = 0; i < 4; i++)
                #pragma unroll
                for (int j = 0; j < 4; j++)
                    FMA2(acc[i][j], av[i], bv[j], acc[i][j]);
        }
        __syncthreads();
    }

    float sc[8], sh[8];
    #pragma unroll
    for (int j = 0; j < 8; j++) {
        int n = n0 + bn + j;
        float inv = rsqrtf(var[n] + EPSF);
        sc[j] = gam[n] * inv;
        sh[j] = bet[n] - mu[n] * sc[j];
    }
    u64 sc2[4], sh2[4];
    #pragma unroll
    for (int j = 0; j < 4; j++) {
        PACK2(sc2[j], sc[2*j], sc[2*j+1]);
        PACK2(sh2[j], sh[2*j], sh[2*j+1]);
    }
    #pragma unroll
    for (int i = 0; i < 4; i++) {
        size_t row = (size_t)(m0 + ty*4 + i) * HH + n0 + bn;
        u64 o[4];
        #pragma unroll
        for (int j = 0; j < 4; j++) FMA2(o[j], acc[i][j], sc2[j], sh2[j]);
        ulonglong2 s0; s0.x = o[0]; s0.y = o[1];
        ulonglong2 s1; s1.x = o[2]; s1.y = o[3];
        *(ulonglong2*)(C + row)     = s0;
        *(ulonglong2*)(C + row + 4) = s1;
    }
}

// =================================================================
// persistent liGRU scan v3.
// 128 CTAs x 256 thr.  CTA owns 8 cols as 2 quads x 2 pairs.
// thread = (qd=tid>>7, bh=(tid>>6)&1, kg=tid&63):
//   4 cols (quad qd, packed pairs), 8 batches (half bh), 16 k's.
// U register-stationary (64 u64).  h in smem [b][k] (no padding,
// contiguous wavefronts).  k-partials -> red smem, 4-warp reduce,
// shfl_xor(16) z/a partner exchange, gate on 64 threads.  Flag
// barrier + linear aligned hT reload.
// =================================================================
__global__ void __launch_bounds__(256, 1) scan_kernel(
    const float* __restrict__ WH, const float* __restrict__ WZ,
    const float* __restrict__ Uh, const float* __restrict__ Uz,
    float* __restrict__ Hout, float* __restrict__ hT,
    int* __restrict__ flags)
{
    extern __shared__ float smem[];
    float* hs  = smem;                       // [16][1024]
    u64*   red = (u64*)(smem + BB*HH);       // [128][REDS]

    int tid = threadIdx.x;
    int qd  = tid >> 7;            // 0..1 quad
    int bh  = (tid >> 6) & 1;      // 0..1 batch-half
    int kg  = tid & 63;            // 0..63 k-slice
    int j0  = blockIdx.x * 8;

    // ---- stationary U in registers: pair-packed ----
    u64 uz[2][16], uh[2][16];
    #pragma unroll
    for (int pr = 0; pr < 2; pr++) {
        const float* z0 = Uz + (size_t)(j0 + qd*4 + 2*pr)*HH;
        const float* z1 = z0 + HH;
        const float* a0 = Uh + (size_t)(j0 + qd*4 + 2*pr)*HH;
        const float* a1 = a0 + HH;
        #pragma unroll
        for (int kk = 0; kk < 16; kk++) {
            int k = kg + (kk << 6);
            PACK2(uz[pr][kk], z0[k], z1[k]);
            PACK2(uh[pr][kk], a0[k], a1[k]);
        }
    }
    for (int idx = tid; idx < BB*HH; idx += 256) hs[idx] = 0.f;   // h0 = 0
    __syncthreads();

    // reduce/gate constants (reduce thread r = tid < 128 handles row r;
    // row r = grp*16 + b, grp = qd*4 + pr*2 + m;  m==0 threads gate)
    int r_b   = tid & 15;
    int r_grp = tid >> 4;            // 0..7 for tid<128
    int r_m   = r_grp & 1;
    int g_qd  = (r_grp >> 2) & 1;
    int g_pr  = (r_grp >> 1) & 1;
    int jg    = j0 + g_qd*4 + g_pr*2;
    bool is_red  = (tid < 128);
    bool is_gate = is_red && (r_m == 0);

    for (int t = 0; t < TT; t++) {
        // prefetch pre-projections (gate threads), hidden behind FMAs
        float2 wz2 = make_float2(0.f, 0.f), wh2 = wz2;
        size_t ob = 0;
        if (is_gate) {
            ob = ((size_t)t*BB + r_b)*HH + jg;
            wz2 = *(const float2*)(WZ + ob);
            wh2 = *(const float2*)(WH + ob);
        }

        // ---- compute: 4 cols x 8 b x 16 k per thread ----
        u64 az[2][8], ah[2][8];
        #pragma unroll
        for (int pr = 0; pr < 2; pr++)
            #pragma unroll
            for (int b = 0; b < 8; b++) { az[pr][b] = 0ull; ah[pr][b] = 0ull; }

        {
            const float* hb = hs + (bh << 3)*HH + kg;
            #pragma unroll
            for (int kk = 0; kk < 16; kk++) {
                const float* hk = hb + (kk << 6);
                #pragma unroll
                for (int b = 0; b < 8; b++) {
                    float hv = hk[b*HH];
                    u64 hd; PACK2(hd, hv, hv);
                    FMA2(az[0][b], hd, uz[0][kk], az[0][b]);
                    FMA2(ah[0][b], hd, uh[0][kk], ah[0][b]);
                    FMA2(az[1][b], hd, uz[1][kk], az[1][b]);
                    FMA2(ah[1][b], hd, uh[1][kk], ah[1][b]);
                }
            }
        }

        // ---- k-partial write: red[grp*16 + b][kg] ----
        {
            u64* rp = red + kg;
            #pragma unroll
            for (int pr = 0; pr < 2; pr++)
                #pragma unroll
                for (int b = 0; b < 8; b++) {
                    int bb = (bh << 3) + b;
                    rp[((qd*4 + pr*2    )*16 + bb)*REDS] = az[pr][b];
                    rp[((qd*4 + pr*2 + 1)*16 + bb)*REDS] = ah[pr][b];
                }
        }
        __syncthreads();

        // ---- 4-warp reduce + partner exchange + gate ----
        if (is_red) {
            const u64* rr = red + (size_t)tid*REDS;
            u64 s0 = 0ull, s1 = 0ull, s2 = 0ull, s3 = 0ull;
            #pragma unroll
            for (int i = 0; i < 64; i += 4) {
                ADD2(s0, s0, rr[i]);
                ADD2(s1, s1, rr[i+1]);
                ADD2(s2, s2, rr[i+2]);
                ADD2(s3, s3, rr[i+3]);
            }
            ADD2(s0, s0, s1);
            ADD2(s2, s2, s3);
            ADD2(s0, s0, s2);
            // rows r and r+16 (z,a of same output pair) sit in lanes l, l^16
            u64 part = __shfl_xor_sync(0xffffffffu, s0, 16);
            if (is_gate) {
                float z0, z1, a0, a1;
                UNPACK2(z0, z1, s0);
                UNPACK2(a0, a1, part);
                float zt0 = 1.f / (1.f + __expf(-(wz2.x + z0)));
                float zt1 = 1.f / (1.f + __expf(-(wz2.y + z1)));
                float hc0 = fmaxf(wh2.x + a0, 0.f) * KEEPF;
                float hc1 = fmaxf(wh2.y + a1, 0.f) * KEEPF;
                float2 ho = *(const float2*)(hs + r_b*HH + jg);
                float2 hn;
                hn.x = zt0*ho.x + (1.f - zt0)*hc0;
                hn.y = zt1*ho.y + (1.f - zt1)*hc1;
                *(float2*)(Hout + ob)        = hn;
                *(float2*)(hT + r_b*HH + jg) = hn;
            }
        }
        __syncthreads();
        if (t == TT-1) break;

        // ---- release/acquire distributed-flag grid barrier ----
        if (tid == 0) {
            asm volatile("st.release.gpu.global.s32 [%0], %1;"
                         :: "l"(flags + blockIdx.x*FPAD), "r"(t+1) : "memory");
        }
        if (tid < GRID_SCAN) {
            const int* fp = flags + tid*FPAD;
            int v;
            do {
                asm volatile("ld.acquire.gpu.global.s32 %0, [%1];"
                             : "=r"(v) : "l"(fp) : "memory");
            } while (v <= t);
        }
        __syncthreads();

        // ---- linear aligned reload: hT [b][k] -> hs [b][k] ----
        {
            const float4* src = (const float4*)hT;
            float4* dst = (float4*)hs;
            #pragma unroll
            for (int i = 0; i < 16; i++)
                dst[tid + (i << 8)] = __ldcg(src + tid + (i << 8));
        }
        __syncthreads();
    }
}

// =================================================================
extern "C" void kernel_launch(void* const* d_in, const int* in_sizes, int n_in,
                              void* d_out, int out_size)
{
    const float* x     = (const float*)d_in[0];
    const int*   x_len = (const int*)  d_in[1];
    const float* whW0  = (const float*)d_in[2];
    const float* wzW0  = (const float*)d_in[3];
    const float* uhW0  = (const float*)d_in[4];
    const float* uzW0  = (const float*)d_in[5];
    const float* bnh_g0 = (const float*)d_in[6];
    const float* bnh_b0 = (const float*)d_in[7];
    const float* bnh_m0 = (const float*)d_in[8];
    const float* bnh_v0 = (const float*)d_in[9];
    const float* bnz_g0 = (const float*)d_in[10];
    const float* bnz_b0 = (const float*)d_in[11];
    const float* bnz_m0 = (const float*)d_in[12];
    const float* bnz_v0 = (const float*)d_in[13];
    const float* whW1  = (const float*)d_in[14];
    const float* wzW1  = (const float*)d_in[15];
    const float* uhW1  = (const float*)d_in[16];
    const float* uzW1  = (const float*)d_in[17];
    const float* bnh_g1 = (const float*)d_in[18];
    const float* bnh_b1 = (const float*)d_in[19];
    const float* bnh_m1 = (const float*)d_in[20];
    const float* bnh_v1 = (const float*)d_in[21];
    const float* bnz_g1 = (const float*)d_in[22];
    const float* bnz_b1 = (const float*)d_in[23];
    const float* bnz_m1 = (const float*)d_in[24];
    const float* bnz_v1 = (const float*)d_in[25];

    float* out = (float*)d_out;

    float *p_wh, *p_wz, *p_h0, *p_hT; int* p_fl;
    cudaGetSymbolAddress((void**)&p_wh, g_wh);
    cudaGetSymbolAddress((void**)&p_wz, g_wz);
    cudaGetSymbolAddress((void**)&p_h0, g_h0);
    cudaGetSymbolAddress((void**)&p_hT, g_hT);
    cudaGetSymbolAddress((void**)&p_fl, g_flags);

    int smem_scan = BB*HH*(int)sizeof(float) + 128*REDS*(int)sizeof(u64); // 132096
    cudaFuncSetAttribute(scan_kernel,
        cudaFuncAttributeMaxDynamicSharedMemorySize, smem_scan);

    init_kernel<<<32, 256>>>(x_len, out, out_size);

    dim3 gg(HH/128, (TT*BB)/64);   // (8, 375)

    // ---- layer 0 ----
    gemm_bn_kernel<<<gg, 256>>>(x, whW0, p_wh, bnh_g0, bnh_b0, bnh_m0, bnh_v0, DD);
    gemm_bn_kernel<<<gg, 256>>>(x, wzW0, p_wz, bnz_g0, bnz_b0, bnz_m0, bnz_v0, DD);
    scan_kernel<<<GRID_SCAN, 256, smem_scan>>>(p_wh, p_wz, uhW0, uzW0, p_h0, p_hT, p_fl);

    // ---- layer 1 ----
    gemm_bn_kernel<<<gg, 256>>>(p_h0, whW1, p_wh, bnh_g1, bnh_b1, bnh_m1, bnh_v1, HH);
    gemm_bn_kernel<<<gg, 256>>>(p_h0, wzW1, p_wz, bnz_g1, bnz_b1, bnz_m1, bnz_v1, HH);
    scan_kernel<<<GRID_SCAN, 256, smem_scan>>>(p_wh, p_wz, uhW1, uzW1, out, p_hT,
                                               p_fl + GRID_SCAN*FPAD);
}